// round 12
// baseline (speedup 1.0000x reference)
#include <cuda_runtime.h>
#include <cuda_fp16.h>
#include <cstdint>
#include <mma.h>
#include <math.h>

using namespace nvcuda;

// gates[4096,4096] = [x|h0] @ [w_ih|w_hh]^T, then LSTM nonlinearity.
constexpr int Bsz  = 4096;
constexpr int Hsz  = 1024;
constexpr int KTOT = 2048;

// CTA 128x128 (8 warps, warp tile 64x32 wmma), BK=64, 3-stage cp.async.
constexpr int BM = 128;
constexpr int BK = 64;
constexpr int NSTAGE = 3;
constexpr int LDA = 72;          // halves; 144B rows, LDSM conflict-free
constexpr int LDG = 132;         // epilogue gate-tile stride (floats)

constexpr int STAGE_HALVES = BM * LDA;                       // 9216 per matrix
constexpr int STAGE_BYTES  = 2 * STAGE_HALVES * 2;           // 36864 (A+B)
constexpr int SMEM_BYTES   = NSTAGE * STAGE_BYTES;           // 110592

__device__ __half g_Afp16[(size_t)Bsz * KTOT];
__device__ __half g_Wfp16[(size_t)(4 * Hsz) * KTOT];

// ── convert kernel: fuse + downconvert to fp16 ──────────────────────────────
__global__ void __launch_bounds__(256)
convert_kernel(const float* __restrict__ x,
               const float* __restrict__ h0,
               const float* __restrict__ w_ih,
               const float* __restrict__ w_hh)
{
    const size_t t = (size_t)blockIdx.x * 256 + threadIdx.x;
    const size_t row = t >> 8;
    const size_t ck  = (t & 255) * 8;

    const float* asrc = (ck < 1024) ? (x    + ck) : (h0   + ck - 1024);
    const float* wsrc = (ck < 1024) ? (w_ih + ck) : (w_hh + ck - 1024);

    float4 a0 = *reinterpret_cast<const float4*>(asrc + row * 1024);
    float4 a1 = *reinterpret_cast<const float4*>(asrc + row * 1024 + 4);
    float4 w0 = *reinterpret_cast<const float4*>(wsrc + row * 1024);
    float4 w1 = *reinterpret_cast<const float4*>(wsrc + row * 1024 + 4);

    __half2 ha[4] = {
        __float22half2_rn(make_float2(a0.x, a0.y)),
        __float22half2_rn(make_float2(a0.z, a0.w)),
        __float22half2_rn(make_float2(a1.x, a1.y)),
        __float22half2_rn(make_float2(a1.z, a1.w))};
    __half2 hw[4] = {
        __float22half2_rn(make_float2(w0.x, w0.y)),
        __float22half2_rn(make_float2(w0.z, w0.w)),
        __float22half2_rn(make_float2(w1.x, w1.y)),
        __float22half2_rn(make_float2(w1.z, w1.w))};

    *reinterpret_cast<uint4*>(&g_Afp16[row * KTOT + ck]) = *reinterpret_cast<uint4*>(ha);
    *reinterpret_cast<uint4*>(&g_Wfp16[row * KTOT + ck]) = *reinterpret_cast<uint4*>(hw);
}

__device__ __forceinline__ void cp16(void* s, const void* g) {
    unsigned int sa = (unsigned int)__cvta_generic_to_shared(s);
    asm volatile("cp.async.cg.shared.global [%0], [%1], 16;"
                 :: "r"(sa), "l"(g) : "memory");
}

__device__ __forceinline__ float fast_sigmoid(float x) {
    return __fdividef(1.0f, 1.0f + __expf(-x));
}
__device__ __forceinline__ float fast_tanh(float x) {
    return __fdividef(2.0f, 1.0f + __expf(-2.0f * x)) - 1.0f;
}

// ── fused GEMM + LSTM kernel ────────────────────────────────────────────────
__global__ void __launch_bounds__(256, 2)
lstm_fp16_kernel(const float* __restrict__ c0,
                 const float* __restrict__ b_ih,
                 const float* __restrict__ b_hh,
                 float* __restrict__ out)
{
    extern __shared__ __align__(16) char smraw[];
    __half* const sm0 = reinterpret_cast<__half*>(smraw);

    const int jt  = blockIdx.x;      // 32 hidden cols per CTA
    const int mt  = blockIdx.y;      // 128 batch rows per CTA
    const int tid = threadIdx.x;
    const int warp = tid >> 5;
    const int wm = warp >> 2;        // 0..1 -> 64 M rows
    const int wn = warp & 3;         // 0..3 -> gate, 32 N cols

    const int aRow0 = mt * BM;

    // per-thread loader geometry: q = tid + i*256 -> r = (tid>>3) + 32i, c4 = tid&7
    const int rA0 = tid >> 3;
    const int c4  = tid & 7;
    const __half* gA = g_Afp16 + (size_t)(aRow0 + rA0) * KTOT + c4 * 8;
    const __half* gB = g_Wfp16 +
        (size_t)((rA0 >> 5) * Hsz + jt * 32 + (rA0 & 31)) * KTOT + c4 * 8;
    const int smoff = rA0 * LDA + c4 * 8;

    wmma::fragment<wmma::accumulator, 16, 16, 16, float> c_frag[4][2];
    #pragma unroll
    for (int a = 0; a < 4; a++)
        #pragma unroll
        for (int b = 0; b < 2; b++)
            wmma::fill_fragment(c_frag[a][b], 0.0f);

    auto issueA = [&](int s) {
        __half* sA = sm0 + (size_t)s * 2 * STAGE_HALVES + smoff;
        #pragma unroll
        for (int i = 0; i < 4; i++)
            cp16(sA + i * (32 * LDA), gA + (size_t)i * (32 * KTOT));
        gA += BK;
    };
    auto issueB = [&](int s) {
        __half* sB = sm0 + (size_t)s * 2 * STAGE_HALVES + STAGE_HALVES + smoff;
        #pragma unroll
        for (int i = 0; i < 4; i++)
            cp16(sB + i * (32 * LDA), gB + (size_t)i * (1024 * KTOT));
        gB += BK;
        asm volatile("cp.async.commit_group;" ::: "memory");
    };

    constexpr int NIT = KTOT / BK;   // 32
    issueA(0); issueB(0);
    issueA(1); issueB(1);

    int cs = 0;   // consume stage
    int ps = 2;   // prefetch stage

    for (int it = 0; it < NIT; ++it) {
        if (it == NIT - 1)
            asm volatile("cp.async.wait_group 0;" ::: "memory");
        else
            asm volatile("cp.async.wait_group 1;" ::: "memory");
        __syncthreads();

        const __half* as = sm0 + (size_t)cs * 2 * STAGE_HALVES;
        const __half* ws = as + STAGE_HALVES;
        cs = (cs == NSTAGE - 1) ? 0 : cs + 1;

        const bool pf = (it + 2 < NIT);

        #pragma unroll
        for (int kk = 0; kk < BK; kk += 16) {
            wmma::fragment<wmma::matrix_a, 16, 16, 16, __half, wmma::row_major> a_frag[4];
            wmma::fragment<wmma::matrix_b, 16, 16, 16, __half, wmma::col_major> b_frag[2];
            #pragma unroll
            for (int im = 0; im < 4; im++)
                wmma::load_matrix_sync(a_frag[im], as + (wm * 64 + im * 16) * LDA + kk, LDA);
            #pragma unroll
            for (int in = 0; in < 2; in++)
                wmma::load_matrix_sync(b_frag[in], ws + (wn * 32 + in * 16) * LDA + kk, LDA);
            #pragma unroll
            for (int im = 0; im < 4; im++)
                #pragma unroll
                for (int in = 0; in < 2; in++)
                    wmma::mma_sync(c_frag[im][in], a_frag[im], b_frag[in], c_frag[im][in]);

            if (kk == 16 && pf) issueA(ps);
            if (kk == 48 && pf) {
                issueB(ps);
                ps = (ps == NSTAGE - 1) ? 0 : ps + 1;
            }
        }
    }
    __syncthreads();

    // ── epilogue: exchange gates via smem, apply LSTM nonlinearity ──
    float* G = reinterpret_cast<float*>(smraw);       // [BM][LDG]
    float* bsum = G + BM * LDG;                       // 128 floats (gate*32 + j)
    #pragma unroll
    for (int im = 0; im < 4; im++)
        #pragma unroll
        for (int in = 0; in < 2; in++)
            wmma::store_matrix_sync(&G[(wm * 64 + im * 16) * LDG + wn * 32 + in * 16],
                                    c_frag[im][in], LDG, wmma::mem_row_major);
    if (tid < 128) {
        const int g = tid >> 5;
        const int jg = jt * 32 + (tid & 31);
        bsum[tid] = b_ih[g * Hsz + jg] + b_hh[g * Hsz + jg];
    }
    __syncthreads();

    // vectorized epilogue: each thread owns 4 consecutive j, 4 m-rows
    {
        const int j4 = (tid & 7) * 4;        // 0..28, constant per thread
        const int m0 = tid >> 3;             // base m row
        const int jg = jt * 32 + j4;

        const float4 bi4 = *reinterpret_cast<const float4*>(&bsum[      j4]);
        const float4 bf4 = *reinterpret_cast<const float4*>(&bsum[ 32 + j4]);
        const float4 bg4 = *reinterpret_cast<const float4*>(&bsum[ 64 + j4]);
        const float4 bo4 = *reinterpret_cast<const float4*>(&bsum[ 96 + j4]);

        #pragma unroll
        for (int k = 0; k < 4; k++) {
            const int m   = m0 + 32 * k;
            const int row = mt * BM + m;

            float4 Gi = *reinterpret_cast<const float4*>(&G[m * LDG +      j4]);
            float4 Gf = *reinterpret_cast<const float4*>(&G[m * LDG + 32 + j4]);
            float4 Gg = *reinterpret_cast<const float4*>(&G[m * LDG + 64 + j4]);
            float4 Go = *reinterpret_cast<const float4*>(&G[m * LDG + 96 + j4]);
            float4 cold = *reinterpret_cast<const float4*>(
                c0 + (size_t)row * Hsz + jg);

            float4 ho, co;
            const float* gip = &Gi.x; const float* gfp = &Gf.x;
            const float* ggp = &Gg.x; const float* gop = &Go.x;
            const float* bip = &bi4.x; const float* bfp = &bf4.x;
            const float* bgp = &bg4.x; const float* bop = &bo4.x;
            const float* cp = &cold.x;
            float* hp = &ho.x; float* ccp = &co.x;

            #pragma unroll
            for (int e = 0; e < 4; e++) {
                float si = fast_sigmoid(gip[e] + bip[e]);
                float sf = fast_sigmoid(gfp[e] + bfp[e]);
                float so = fast_sigmoid(gop[e] + bop[e]);
                float tg = fast_tanh(ggp[e] + bgp[e]);
                float cn = sf * cp[e] + si * tg;
                hp[e]  = so * fast_tanh(cn);
                ccp[e] = cn;
            }

            *reinterpret_cast<float4*>(out + (size_t)row * Hsz + jg) = ho;
            *reinterpret_cast<float4*>(out + (size_t)Bsz * Hsz +
                                       (size_t)row * Hsz + jg) = co;
        }
    }
}

extern "C" void kernel_launch(void* const* d_in, const int* in_sizes, int n_in,
                              void* d_out, int out_size) {
    const float* x    = (const float*)d_in[0];
    const float* h0   = (const float*)d_in[1];
    const float* c0   = (const float*)d_in[2];
    const float* w_ih = (const float*)d_in[3];
    const float* w_hh = (const float*)d_in[4];
    const float* b_ih = (const float*)d_in[5];
    const float* b_hh = (const float*)d_in[6];
    float* out = (float*)d_out;

    cudaFuncSetAttribute(lstm_fp16_kernel,
                         cudaFuncAttributeMaxDynamicSharedMemorySize, SMEM_BYTES);

    convert_kernel<<<4096, 256>>>(x, h0, w_ih, w_hh);

    dim3 grid(Hsz / 32, Bsz / BM);   // (32, 32)
    lstm_fp16_kernel<<<grid, 256, SMEM_BYTES>>>(c0, b_ih, b_hh, out);
}

// round 13
// speedup vs baseline: 1.4359x; 1.4359x over previous
#include <cuda_runtime.h>
#include <cuda_fp16.h>
#include <cstdint>
#include <mma.h>
#include <math.h>

using namespace nvcuda;

// gates[4096,4096] = [x|h0] @ [w_ih|w_hh]^T, then LSTM nonlinearity.
constexpr int Bsz  = 4096;
constexpr int Hsz  = 1024;
constexpr int KTOT = 2048;

// CTA 128x128 (8 warps, warp tile 64x32 wmma), BK=64, 3-stage cp.async.
constexpr int BM = 128;
constexpr int BK = 64;
constexpr int NSTAGE = 3;
constexpr int LDA = 72;          // halves; 144B rows, LDSM conflict-free
constexpr int LDG = 132;         // epilogue gate-tile stride (floats)

constexpr int STAGE_HALVES = BM * LDA;                       // 9216 per matrix
constexpr int STAGE_BYTES  = 2 * STAGE_HALVES * 2;           // 36864 (A+B)
constexpr int SMEM_BYTES   = NSTAGE * STAGE_BYTES;           // 110592

__device__ __half g_Afp16[(size_t)Bsz * KTOT];
__device__ __half g_Wfp16[(size_t)(4 * Hsz) * KTOT];

// ── convert kernel: fuse + downconvert to fp16 ──────────────────────────────
__global__ void __launch_bounds__(256)
convert_kernel(const float* __restrict__ x,
               const float* __restrict__ h0,
               const float* __restrict__ w_ih,
               const float* __restrict__ w_hh)
{
    const size_t t = (size_t)blockIdx.x * 256 + threadIdx.x;
    const size_t row = t >> 8;
    const size_t ck  = (t & 255) * 8;

    const float* asrc = (ck < 1024) ? (x    + ck) : (h0   + ck - 1024);
    const float* wsrc = (ck < 1024) ? (w_ih + ck) : (w_hh + ck - 1024);

    float4 a0 = *reinterpret_cast<const float4*>(asrc + row * 1024);
    float4 a1 = *reinterpret_cast<const float4*>(asrc + row * 1024 + 4);
    float4 w0 = *reinterpret_cast<const float4*>(wsrc + row * 1024);
    float4 w1 = *reinterpret_cast<const float4*>(wsrc + row * 1024 + 4);

    __half2 ha[4] = {
        __float22half2_rn(make_float2(a0.x, a0.y)),
        __float22half2_rn(make_float2(a0.z, a0.w)),
        __float22half2_rn(make_float2(a1.x, a1.y)),
        __float22half2_rn(make_float2(a1.z, a1.w))};
    __half2 hw[4] = {
        __float22half2_rn(make_float2(w0.x, w0.y)),
        __float22half2_rn(make_float2(w0.z, w0.w)),
        __float22half2_rn(make_float2(w1.x, w1.y)),
        __float22half2_rn(make_float2(w1.z, w1.w))};

    *reinterpret_cast<uint4*>(&g_Afp16[row * KTOT + ck]) = *reinterpret_cast<uint4*>(ha);
    *reinterpret_cast<uint4*>(&g_Wfp16[row * KTOT + ck]) = *reinterpret_cast<uint4*>(hw);
}

__device__ __forceinline__ void cp16(void* s, const void* g) {
    unsigned int sa = (unsigned int)__cvta_generic_to_shared(s);
    asm volatile("cp.async.cg.shared.global [%0], [%1], 16;"
                 :: "r"(sa), "l"(g) : "memory");
}

__device__ __forceinline__ float fast_sigmoid(float x) {
    return __fdividef(1.0f, 1.0f + __expf(-x));
}
__device__ __forceinline__ float fast_tanh(float x) {
    return __fdividef(2.0f, 1.0f + __expf(-2.0f * x)) - 1.0f;
}

// ── fused GEMM + LSTM kernel ────────────────────────────────────────────────
__global__ void __launch_bounds__(256, 2)
lstm_fp16_kernel(const float* __restrict__ c0,
                 const float* __restrict__ b_ih,
                 const float* __restrict__ b_hh,
                 float* __restrict__ out)
{
    extern __shared__ __align__(16) char smraw[];
    __half* const sm0 = reinterpret_cast<__half*>(smraw);

    const int jt  = blockIdx.x;      // 32 hidden cols per CTA
    const int mt  = blockIdx.y;      // 128 batch rows per CTA
    const int tid = threadIdx.x;
    const int warp = tid >> 5;
    const int wm = warp >> 2;        // 0..1 -> 64 M rows
    const int wn = warp & 3;         // 0..3 -> gate, 32 N cols

    const int aRow0 = mt * BM;

    // per-thread loader geometry: q = tid + i*256 -> r = (tid>>3) + 32i, c4 = tid&7
    const int rA0 = tid >> 3;
    const int c4  = tid & 7;
    const __half* gA = g_Afp16 + (size_t)(aRow0 + rA0) * KTOT + c4 * 8;
    const __half* gB = g_Wfp16 +
        (size_t)((rA0 >> 5) * Hsz + jt * 32 + (rA0 & 31)) * KTOT + c4 * 8;
    const int smoff = rA0 * LDA + c4 * 8;

    wmma::fragment<wmma::accumulator, 16, 16, 16, float> c_frag[4][2];
    #pragma unroll
    for (int a = 0; a < 4; a++)
        #pragma unroll
        for (int b = 0; b < 2; b++)
            wmma::fill_fragment(c_frag[a][b], 0.0f);

    auto issueA = [&](int s) {
        __half* sA = sm0 + (size_t)s * 2 * STAGE_HALVES + smoff;
        #pragma unroll
        for (int i = 0; i < 4; i++)
            cp16(sA + i * (32 * LDA), gA + (size_t)i * (32 * KTOT));
        gA += BK;
    };
    auto issueB = [&](int s) {
        __half* sB = sm0 + (size_t)s * 2 * STAGE_HALVES + STAGE_HALVES + smoff;
        #pragma unroll
        for (int i = 0; i < 4; i++)
            cp16(sB + i * (32 * LDA), gB + (size_t)i * (1024 * KTOT));
        gB += BK;
        asm volatile("cp.async.commit_group;" ::: "memory");
    };

    constexpr int NIT = KTOT / BK;   // 32
    issueA(0); issueB(0);
    issueA(1); issueB(1);

    int cs = 0;   // consume stage
    int ps = 2;   // prefetch stage

    for (int it = 0; it < NIT; ++it) {
        if (it == NIT - 1)
            asm volatile("cp.async.wait_group 0;" ::: "memory");
        else
            asm volatile("cp.async.wait_group 1;" ::: "memory");
        __syncthreads();

        const __half* as = sm0 + (size_t)cs * 2 * STAGE_HALVES;
        const __half* ws = as + STAGE_HALVES;
        cs = (cs == NSTAGE - 1) ? 0 : cs + 1;

        const bool pf = (it + 2 < NIT);

        #pragma unroll
        for (int kk = 0; kk < BK; kk += 16) {
            wmma::fragment<wmma::matrix_a, 16, 16, 16, __half, wmma::row_major> a_frag[4];
            wmma::fragment<wmma::matrix_b, 16, 16, 16, __half, wmma::col_major> b_frag[2];
            #pragma unroll
            for (int im = 0; im < 4; im++)
                wmma::load_matrix_sync(a_frag[im], as + (wm * 64 + im * 16) * LDA + kk, LDA);
            #pragma unroll
            for (int in = 0; in < 2; in++)
                wmma::load_matrix_sync(b_frag[in], ws + (wn * 32 + in * 16) * LDA + kk, LDA);
            #pragma unroll
            for (int im = 0; im < 4; im++)
                #pragma unroll
                for (int in = 0; in < 2; in++)
                    wmma::mma_sync(c_frag[im][in], a_frag[im], b_frag[in], c_frag[im][in]);

            if (kk == 16 && pf) issueA(ps);
            if (kk == 48 && pf) {
                issueB(ps);
                ps = (ps == NSTAGE - 1) ? 0 : ps + 1;
            }
        }
    }
    __syncthreads();

    // ── epilogue: exchange gates via smem, apply LSTM nonlinearity ──
    float* G = reinterpret_cast<float*>(smraw);       // [BM][LDG]
    float* bsum = G + BM * LDG;                       // 128 floats (gate*32 + j)
    #pragma unroll
    for (int im = 0; im < 4; im++)
        #pragma unroll
        for (int in = 0; in < 2; in++)
            wmma::store_matrix_sync(&G[(wm * 64 + im * 16) * LDG + wn * 32 + in * 16],
                                    c_frag[im][in], LDG, wmma::mem_row_major);
    if (tid < 128) {
        const int g = tid >> 5;
        const int jg = jt * 32 + (tid & 31);
        bsum[tid] = b_ih[g * Hsz + jg] + b_hh[g * Hsz + jg];
    }
    __syncthreads();

    {
        const int j = tid & 31;                        // constant per thread
        const float bi = bsum[      j];
        const float bf = bsum[ 32 + j];
        const float bg = bsum[ 64 + j];
        const float bo = bsum[ 96 + j];
        const int jg = jt * 32 + j;

        for (int idx = tid; idx < BM * 32; idx += 256) {
            int m  = idx >> 5;
            int row = mt * BM + m;

            float gi = G[m * LDG +      j] + bi;
            float gf = G[m * LDG + 32 + j] + bf;
            float gg = G[m * LDG + 64 + j] + bg;
            float go = G[m * LDG + 96 + j] + bo;

            float si = fast_sigmoid(gi);
            float sf = fast_sigmoid(gf);
            float so = fast_sigmoid(go);
            float tg = fast_tanh(gg);

            float cold = c0[(size_t)row * Hsz + jg];
            float cn = sf * cold + si * tg;
            float hn = so * fast_tanh(cn);

            out[(size_t)row * Hsz + jg]                     = hn;
            out[(size_t)Bsz * Hsz + (size_t)row * Hsz + jg] = cn;
        }
    }
}

extern "C" void kernel_launch(void* const* d_in, const int* in_sizes, int n_in,
                              void* d_out, int out_size) {
    const float* x    = (const float*)d_in[0];
    const float* h0   = (const float*)d_in[1];
    const float* c0   = (const float*)d_in[2];
    const float* w_ih = (const float*)d_in[3];
    const float* w_hh = (const float*)d_in[4];
    const float* b_ih = (const float*)d_in[5];
    const float* b_hh = (const float*)d_in[6];
    float* out = (float*)d_out;

    cudaFuncSetAttribute(lstm_fp16_kernel,
                         cudaFuncAttributeMaxDynamicSharedMemorySize, SMEM_BYTES);

    convert_kernel<<<4096, 256>>>(x, h0, w_ih, w_hh);

    dim3 grid(Hsz / 32, Bsz / BM);   // (32, 32)
    lstm_fp16_kernel<<<grid, 256, SMEM_BYTES>>>(c0, b_ih, b_hh, out);
}

// round 14
// speedup vs baseline: 1.4999x; 1.0446x over previous
#include <cuda_runtime.h>
#include <cuda_fp16.h>
#include <cstdint>
#include <mma.h>
#include <math.h>

using namespace nvcuda;

// gates[4096,4096] = [x|h0] @ [w_ih|w_hh]^T, then LSTM nonlinearity.
constexpr int Bsz  = 4096;
constexpr int Hsz  = 1024;
constexpr int KTOT = 2048;

// CTA 128x128 (8 warps, warp tile 64x32 wmma), BK=64, 3-stage cp.async.
constexpr int BM = 128;
constexpr int BK = 64;
constexpr int NSTAGE = 3;
constexpr int LDA = 72;          // halves; 144B rows, LDSM conflict-free
constexpr int LDG = 132;         // epilogue gate-tile stride (floats)

constexpr int STAGE_HALVES = BM * LDA;                       // 9216 per matrix
constexpr int STAGE_BYTES  = 2 * STAGE_HALVES * 2;           // 36864 (A+B)
constexpr int SMEM_BYTES   = NSTAGE * STAGE_BYTES;           // 110592

__device__ __half g_Afp16[(size_t)Bsz * KTOT];
__device__ __half g_Wfp16[(size_t)(4 * Hsz) * KTOT];

// ── convert kernel: fuse + downconvert to fp16 ──────────────────────────────
__global__ void __launch_bounds__(256)
convert_kernel(const float* __restrict__ x,
               const float* __restrict__ h0,
               const float* __restrict__ w_ih,
               const float* __restrict__ w_hh)
{
    const size_t t = (size_t)blockIdx.x * 256 + threadIdx.x;
    const size_t row = t >> 8;
    const size_t ck  = (t & 255) * 8;

    const float* asrc = (ck < 1024) ? (x    + ck) : (h0   + ck - 1024);
    const float* wsrc = (ck < 1024) ? (w_ih + ck) : (w_hh + ck - 1024);

    float4 a0 = *reinterpret_cast<const float4*>(asrc + row * 1024);
    float4 a1 = *reinterpret_cast<const float4*>(asrc + row * 1024 + 4);
    float4 w0 = *reinterpret_cast<const float4*>(wsrc + row * 1024);
    float4 w1 = *reinterpret_cast<const float4*>(wsrc + row * 1024 + 4);

    __half2 ha[4] = {
        __float22half2_rn(make_float2(a0.x, a0.y)),
        __float22half2_rn(make_float2(a0.z, a0.w)),
        __float22half2_rn(make_float2(a1.x, a1.y)),
        __float22half2_rn(make_float2(a1.z, a1.w))};
    __half2 hw[4] = {
        __float22half2_rn(make_float2(w0.x, w0.y)),
        __float22half2_rn(make_float2(w0.z, w0.w)),
        __float22half2_rn(make_float2(w1.x, w1.y)),
        __float22half2_rn(make_float2(w1.z, w1.w))};

    *reinterpret_cast<uint4*>(&g_Afp16[row * KTOT + ck]) = *reinterpret_cast<uint4*>(ha);
    *reinterpret_cast<uint4*>(&g_Wfp16[row * KTOT + ck]) = *reinterpret_cast<uint4*>(hw);
}

__device__ __forceinline__ void cp16(void* s, const void* g) {
    unsigned int sa = (unsigned int)__cvta_generic_to_shared(s);
    asm volatile("cp.async.cg.shared.global [%0], [%1], 16;"
                 :: "r"(sa), "l"(g) : "memory");
}

__device__ __forceinline__ float fast_sigmoid(float x) {
    return __fdividef(1.0f, 1.0f + __expf(-x));
}
__device__ __forceinline__ float fast_tanh(float x) {
    return __fdividef(2.0f, 1.0f + __expf(-2.0f * x)) - 1.0f;
}

// ── fused GEMM + LSTM kernel ────────────────────────────────────────────────
__global__ void __launch_bounds__(256, 2)
lstm_fp16_kernel(const float* __restrict__ c0,
                 const float* __restrict__ b_ih,
                 const float* __restrict__ b_hh,
                 float* __restrict__ out)
{
    extern __shared__ __align__(16) char smraw[];
    __half* const sm0 = reinterpret_cast<__half*>(smraw);

    const int jt  = blockIdx.x;      // 32 hidden cols per CTA
    const int mt  = blockIdx.y;      // 128 batch rows per CTA
    const int tid = threadIdx.x;
    const int warp = tid >> 5;
    const int wm = warp >> 2;        // 0..1 -> 64 M rows
    const int wn = warp & 3;         // 0..3 -> gate, 32 N cols

    const int aRow0 = mt * BM;

    // per-thread loader geometry: q = tid + i*256 -> r = (tid>>3) + 32i, c4 = tid&7
    const int rA0 = tid >> 3;
    const int c4  = tid & 7;
    const __half* gA = g_Afp16 + (size_t)(aRow0 + rA0) * KTOT + c4 * 8;
    const __half* gB = g_Wfp16 +
        (size_t)((rA0 >> 5) * Hsz + jt * 32 + (rA0 & 31)) * KTOT + c4 * 8;
    const int smoff = rA0 * LDA + c4 * 8;

    wmma::fragment<wmma::accumulator, 16, 16, 16, float> c_frag[4][2];
    #pragma unroll
    for (int a = 0; a < 4; a++)
        #pragma unroll
        for (int b = 0; b < 2; b++)
            wmma::fill_fragment(c_frag[a][b], 0.0f);

    auto issueA = [&](int s) {   // s is a compile-time literal at every call site
        __half* sA = sm0 + s * 2 * STAGE_HALVES + smoff;
        #pragma unroll
        for (int i = 0; i < 4; i++)
            cp16(sA + i * (32 * LDA), gA + (size_t)i * (32 * KTOT));
        gA += BK;
    };
    auto issueB = [&](int s) {
        __half* sB = sm0 + s * 2 * STAGE_HALVES + STAGE_HALVES + smoff;
        #pragma unroll
        for (int i = 0; i < 4; i++)
            cp16(sB + i * (32 * LDA), gB + (size_t)i * (1024 * KTOT));
        gB += BK;
        asm volatile("cp.async.commit_group;" ::: "memory");
    };

    constexpr int NIT = KTOT / BK;   // 32
    issueA(0); issueB(0);
    issueA(1); issueB(1);

    // one pipeline step; cs/ps are literals at every call site
    auto body = [&](int it, int cs, int ps, bool last) {
        if (last)
            asm volatile("cp.async.wait_group 0;" ::: "memory");
        else
            asm volatile("cp.async.wait_group 1;" ::: "memory");
        __syncthreads();

        const __half* as = sm0 + cs * 2 * STAGE_HALVES;
        const __half* ws = as + STAGE_HALVES;
        const bool pf = (it + 2 < NIT);

        #pragma unroll
        for (int kk = 0; kk < BK; kk += 16) {
            wmma::fragment<wmma::matrix_a, 16, 16, 16, __half, wmma::row_major> a_frag[4];
            wmma::fragment<wmma::matrix_b, 16, 16, 16, __half, wmma::col_major> b_frag[2];
            #pragma unroll
            for (int im = 0; im < 4; im++)
                wmma::load_matrix_sync(a_frag[im], as + (wm * 64 + im * 16) * LDA + kk, LDA);
            #pragma unroll
            for (int in = 0; in < 2; in++)
                wmma::load_matrix_sync(b_frag[in], ws + (wn * 32 + in * 16) * LDA + kk, LDA);
            #pragma unroll
            for (int im = 0; im < 4; im++)
                #pragma unroll
                for (int in = 0; in < 2; in++)
                    wmma::mma_sync(c_frag[im][in], a_frag[im], b_frag[in], c_frag[im][in]);

            if (kk == 16 && pf) issueA(ps);
            if (kk == 48 && pf) issueB(ps);
        }
    };

    // 30 iterations in groups of 3 (stage pattern repeats), then 2-iter tail.
    for (int it = 0; it < NIT - 2; it += 3) {
        body(it,     0, 2, false);
        body(it + 1, 1, 0, false);
        body(it + 2, 2, 1, false);
    }
    body(NIT - 2, 0, 2, false);   // it = 30, stage 0
    body(NIT - 1, 1, 0, true);    // it = 31, stage 1
    __syncthreads();

    // ── epilogue: exchange gates via smem, apply LSTM nonlinearity ──
    float* G = reinterpret_cast<float*>(smraw);       // [BM][LDG]
    float* bsum = G + BM * LDG;                       // 128 floats (gate*32 + j)
    #pragma unroll
    for (int im = 0; im < 4; im++)
        #pragma unroll
        for (int in = 0; in < 2; in++)
            wmma::store_matrix_sync(&G[(wm * 64 + im * 16) * LDG + wn * 32 + in * 16],
                                    c_frag[im][in], LDG, wmma::mem_row_major);
    if (tid < 128) {
        const int g = tid >> 5;
        const int jg = jt * 32 + (tid & 31);
        bsum[tid] = b_ih[g * Hsz + jg] + b_hh[g * Hsz + jg];
    }
    __syncthreads();

    {
        const int j = tid & 31;                        // constant per thread
        const float bi = bsum[      j];
        const float bf = bsum[ 32 + j];
        const float bg = bsum[ 64 + j];
        const float bo = bsum[ 96 + j];
        const int jg = jt * 32 + j;

        for (int idx = tid; idx < BM * 32; idx += 256) {
            int m  = idx >> 5;
            int row = mt * BM + m;

            float gi = G[m * LDG +      j] + bi;
            float gf = G[m * LDG + 32 + j] + bf;
            float gg = G[m * LDG + 64 + j] + bg;
            float go = G[m * LDG + 96 + j] + bo;

            float si = fast_sigmoid(gi);
            float sf = fast_sigmoid(gf);
            float so = fast_sigmoid(go);
            float tg = fast_tanh(gg);

            float cold = c0[(size_t)row * Hsz + jg];
            float cn = sf * cold + si * tg;
            float hn = so * fast_tanh(cn);

            out[(size_t)row * Hsz + jg]                     = hn;
            out[(size_t)Bsz * Hsz + (size_t)row * Hsz + jg] = cn;
        }
    }
}

extern "C" void kernel_launch(void* const* d_in, const int* in_sizes, int n_in,
                              void* d_out, int out_size) {
    const float* x    = (const float*)d_in[0];
    const float* h0   = (const float*)d_in[1];
    const float* c0   = (const float*)d_in[2];
    const float* w_ih = (const float*)d_in[3];
    const float* w_hh = (const float*)d_in[4];
    const float* b_ih = (const float*)d_in[5];
    const float* b_hh = (const float*)d_in[6];
    float* out = (float*)d_out;

    cudaFuncSetAttribute(lstm_fp16_kernel,
                         cudaFuncAttributeMaxDynamicSharedMemorySize, SMEM_BYTES);

    convert_kernel<<<4096, 256>>>(x, h0, w_ih, w_hh);

    dim3 grid(Hsz / 32, Bsz / BM);   // (32, 32)
    lstm_fp16_kernel<<<grid, 256, SMEM_BYTES>>>(c0, b_ih, b_hh, out);
}

// round 16
// speedup vs baseline: 1.5161x; 1.0108x over previous
#include <cuda_runtime.h>
#include <cuda_fp16.h>
#include <cstdint>
#include <mma.h>
#include <math.h>

using namespace nvcuda;

// gates[4096,4096] = [x|h0] @ [w_ih|w_hh]^T, then LSTM nonlinearity.
constexpr int Bsz  = 4096;
constexpr int Hsz  = 1024;
constexpr int KTOT = 2048;

// CTA 128x128 (8 warps, warp tile 64x32 wmma), BK=64, 3-stage cp.async.
constexpr int BM = 128;
constexpr int BK = 64;
constexpr int NSTAGE = 3;
constexpr int LDA = 72;          // halves; 144B rows, LDSM conflict-free
constexpr int LDG = 132;         // epilogue gate-tile stride (floats)

constexpr int STAGE_HALVES = BM * LDA;                       // 9216 per matrix
constexpr int STAGE_BYTES  = 2 * STAGE_HALVES * 2;           // 36864 (A+B)
constexpr int SMEM_BYTES   = NSTAGE * STAGE_BYTES;           // 110592

__device__ __half g_Afp16[(size_t)Bsz * KTOT];
__device__ __half g_Wfp16[(size_t)(4 * Hsz) * KTOT];

// ── convert kernel: fuse + downconvert to fp16 ──────────────────────────────
__global__ void __launch_bounds__(256)
convert_kernel(const float* __restrict__ x,
               const float* __restrict__ h0,
               const float* __restrict__ w_ih,
               const float* __restrict__ w_hh)
{
    const size_t t = (size_t)blockIdx.x * 256 + threadIdx.x;
    const size_t row = t >> 8;
    const size_t ck  = (t & 255) * 8;

    const float* asrc = (ck < 1024) ? (x    + ck) : (h0   + ck - 1024);
    const float* wsrc = (ck < 1024) ? (w_ih + ck) : (w_hh + ck - 1024);

    float4 a0 = *reinterpret_cast<const float4*>(asrc + row * 1024);
    float4 a1 = *reinterpret_cast<const float4*>(asrc + row * 1024 + 4);
    float4 w0 = *reinterpret_cast<const float4*>(wsrc + row * 1024);
    float4 w1 = *reinterpret_cast<const float4*>(wsrc + row * 1024 + 4);

    __half2 ha[4] = {
        __float22half2_rn(make_float2(a0.x, a0.y)),
        __float22half2_rn(make_float2(a0.z, a0.w)),
        __float22half2_rn(make_float2(a1.x, a1.y)),
        __float22half2_rn(make_float2(a1.z, a1.w))};
    __half2 hw[4] = {
        __float22half2_rn(make_float2(w0.x, w0.y)),
        __float22half2_rn(make_float2(w0.z, w0.w)),
        __float22half2_rn(make_float2(w1.x, w1.y)),
        __float22half2_rn(make_float2(w1.z, w1.w))};

    *reinterpret_cast<uint4*>(&g_Afp16[row * KTOT + ck]) = *reinterpret_cast<uint4*>(ha);
    *reinterpret_cast<uint4*>(&g_Wfp16[row * KTOT + ck]) = *reinterpret_cast<uint4*>(hw);
}

__device__ __forceinline__ void cp16(void* s, const void* g) {
    unsigned int sa = (unsigned int)__cvta_generic_to_shared(s);
    asm volatile("cp.async.cg.shared.global [%0], [%1], 16;"
                 :: "r"(sa), "l"(g) : "memory");
}

__device__ __forceinline__ float fast_sigmoid(float x) {
    return __fdividef(1.0f, 1.0f + __expf(-x));
}
__device__ __forceinline__ float fast_tanh(float x) {
    return __fdividef(2.0f, 1.0f + __expf(-2.0f * x)) - 1.0f;
}

// ── fused GEMM + LSTM kernel ────────────────────────────────────────────────
__global__ void __launch_bounds__(256, 2)
lstm_fp16_kernel(const float* __restrict__ c0,
                 const float* __restrict__ b_ih,
                 const float* __restrict__ b_hh,
                 float* __restrict__ out)
{
    extern __shared__ __align__(16) char smraw[];
    __half* const sm0 = reinterpret_cast<__half*>(smraw);

    const int jt  = blockIdx.x;      // 32 hidden cols per CTA
    const int mt  = blockIdx.y;      // 128 batch rows per CTA
    const int tid = threadIdx.x;
    const int warp = tid >> 5;
    const int wm = warp >> 2;        // 0..1 -> 64 M rows
    const int wn = warp & 3;         // 0..3 -> gate, 32 N cols

    const int aRow0 = mt * BM;

    // per-thread loader geometry: q = tid + i*256 -> r = (tid>>3) + 32i, c4 = tid&7
    const int rA0 = tid >> 3;
    const int c4  = tid & 7;
    const __half* gA = g_Afp16 + (size_t)(aRow0 + rA0) * KTOT + c4 * 8;
    const __half* gB = g_Wfp16 +
        (size_t)((rA0 >> 5) * Hsz + jt * 32 + (rA0 & 31)) * KTOT + c4 * 8;
    const int smoff = rA0 * LDA + c4 * 8;

    wmma::fragment<wmma::accumulator, 16, 16, 16, float> c_frag[4][2];
    #pragma unroll
    for (int a = 0; a < 4; a++)
        #pragma unroll
        for (int b = 0; b < 2; b++)
            wmma::fill_fragment(c_frag[a][b], 0.0f);

    auto issueA = [&](int s) {   // s is a compile-time literal at every call site
        __half* sA = sm0 + s * 2 * STAGE_HALVES + smoff;
        #pragma unroll
        for (int i = 0; i < 4; i++)
            cp16(sA + i * (32 * LDA), gA + (size_t)i * (32 * KTOT));
        gA += BK;
    };
    auto issueB = [&](int s) {
        __half* sB = sm0 + s * 2 * STAGE_HALVES + STAGE_HALVES + smoff;
        #pragma unroll
        for (int i = 0; i < 4; i++)
            cp16(sB + i * (32 * LDA), gB + (size_t)i * (1024 * KTOT));
        gB += BK;
        asm volatile("cp.async.commit_group;" ::: "memory");
    };

    constexpr int NIT = KTOT / BK;   // 32
    issueA(0); issueB(0);
    issueA(1); issueB(1);

    // one pipeline step; cs/ps/pf/last are literals at every call site
    auto body = [&](int cs, int ps, bool pf, bool last) {
        if (last)
            asm volatile("cp.async.wait_group 0;" ::: "memory");
        else
            asm volatile("cp.async.wait_group 1;" ::: "memory");
        __syncthreads();

        const __half* as = sm0 + cs * 2 * STAGE_HALVES;
        const __half* ws = as + STAGE_HALVES;

        #pragma unroll
        for (int kk = 0; kk < BK; kk += 16) {
            wmma::fragment<wmma::matrix_a, 16, 16, 16, __half, wmma::row_major> a_frag[4];
            wmma::fragment<wmma::matrix_b, 16, 16, 16, __half, wmma::col_major> b_frag[2];
            #pragma unroll
            for (int im = 0; im < 4; im++)
                wmma::load_matrix_sync(a_frag[im], as + (wm * 64 + im * 16) * LDA + kk, LDA);
            #pragma unroll
            for (int in = 0; in < 2; in++)
                wmma::load_matrix_sync(b_frag[in], ws + (wn * 32 + in * 16) * LDA + kk, LDA);
            #pragma unroll
            for (int im = 0; im < 4; im++)
                #pragma unroll
                for (int in = 0; in < 2; in++)
                    wmma::mma_sync(c_frag[im][in], a_frag[im], b_frag[in], c_frag[im][in]);

            if (kk == 0  && pf) issueA(ps);
            if (kk == 32 && pf) issueB(ps);
        }
    };

    // 30 iterations in groups of 3 (stage pattern repeats, pf always true),
    // then 2-iter tail with pf=false.
    for (int g3 = 0; g3 < (NIT - 2) / 3; ++g3) {
        body(0, 2, true, false);
        body(1, 0, true, false);
        body(2, 1, true, false);
    }
    body(0, 2, false, false);   // it = 30, stage 0
    body(1, 0, false, true);    // it = 31, stage 1
    __syncthreads();

    // ── epilogue: exchange gates via smem, apply LSTM nonlinearity ──
    float* G = reinterpret_cast<float*>(smraw);       // [BM][LDG]
    float* bsum = G + BM * LDG;                       // 128 floats (gate*32 + j)
    #pragma unroll
    for (int im = 0; im < 4; im++)
        #pragma unroll
        for (int in = 0; in < 2; in++)
            wmma::store_matrix_sync(&G[(wm * 64 + im * 16) * LDG + wn * 32 + in * 16],
                                    c_frag[im][in], LDG, wmma::mem_row_major);
    if (tid < 128) {
        const int g = tid >> 5;
        const int jg = jt * 32 + (tid & 31);
        bsum[tid] = b_ih[g * Hsz + jg] + b_hh[g * Hsz + jg];
    }
    __syncthreads();

    {
        const int j = tid & 31;                        // constant per thread
        const float bi = bsum[      j];
        const float bf = bsum[ 32 + j];
        const float bg = bsum[ 64 + j];
        const float bo = bsum[ 96 + j];
        const int jg = jt * 32 + j;

        for (int idx = tid; idx < BM * 32; idx += 256) {
            int m  = idx >> 5;
            int row = mt * BM + m;

            float gi = G[m * LDG +      j] + bi;
            float gf = G[m * LDG + 32 + j] + bf;
            float gg = G[m * LDG + 64 + j] + bg;
            float go = G[m * LDG + 96 + j] + bo;

            float si = fast_sigmoid(gi);
            float sf = fast_sigmoid(gf);
            float so = fast_sigmoid(go);
            float tg = fast_tanh(gg);

            float cold = c0[(size_t)row * Hsz + jg];
            float cn = sf * cold + si * tg;
            float hn = so * fast_tanh(cn);

            out[(size_t)row * Hsz + jg]                     = hn;
            out[(size_t)Bsz * Hsz + (size_t)row * Hsz + jg] = cn;
        }
    }
}

extern "C" void kernel_launch(void* const* d_in, const int* in_sizes, int n_in,
                              void* d_out, int out_size) {
    const float* x    = (const float*)d_in[0];
    const float* h0   = (const float*)d_in[1];
    const float* c0   = (const float*)d_in[2];
    const float* w_ih = (const float*)d_in[3];
    const float* w_hh = (const float*)d_in[4];
    const float* b_ih = (const float*)d_in[5];
    const float* b_hh = (const float*)d_in[6];
    float* out = (float*)d_out;

    cudaFuncSetAttribute(lstm_fp16_kernel,
                         cudaFuncAttributeMaxDynamicSharedMemorySize, SMEM_BYTES);

    convert_kernel<<<4096, 256>>>(x, h0, w_ih, w_hh);

    dim3 grid(Hsz / 32, Bsz / BM);   // (32, 32)
    lstm_fp16_kernel<<<grid, 256, SMEM_BYTES>>>(c0, b_ih, b_hh, out);
}